// round 6
// baseline (speedup 1.0000x reference)
#include <cuda_runtime.h>
#include <cuda_bf16.h>
#include <math.h>
#include <stdint.h>

#define NCLS 5
#define NQ   75
#define NN   80
#define FEAT 640
#define HID  4096
#define DIN  465
#define KPAD 512
#define LRC  1e-3f
#define NBLK 128u
#define NT   256

// ------------------------- scratch (device globals) -------------------------
__device__ __align__(128) float g_supp[NCLS * FEAT];
__device__ __align__(128) float g_query[NQ * FEAT];
__device__ __align__(128) float g_F[NN * FEAT];
__device__ float g_nrm[NN];
__device__ int   g_idx[NN * 81];
__device__ __align__(128) float g_G[NN * NN];
__device__ __align__(128) float g_parts[8 * NN * KPAD];
// activations, BLOCKED: A_blk[kb][80][64] bf16, SW128-swizzled 128B rows
__device__ __align__(1024) __nv_bfloat16 g_xb [NN * KPAD];
__device__ __align__(1024) __nv_bfloat16 g_h1b[NN * HID];
__device__ __align__(1024) __nv_bfloat16 g_h2b[NN * HID];
// weights, BLOCKED: W_blk[nb][kb][32][64] bf16, SW128-swizzled
__device__ __align__(1024) __nv_bfloat16 g_W1b[2][HID * KPAD];
__device__ __align__(1024) __nv_bfloat16 g_W2b[2][HID * HID];
__device__ __align__(1024) __nv_bfloat16 g_W3b[2][KPAD * HID];
// grid barrier state (replay-safe: cnt self-resets, gen only compared relatively)
__device__ unsigned g_cnt;
__device__ unsigned g_gen;

#define SW128(o) ((o) ^ (((o) >> 3) & 0x70))
#define ABLK_OFF(m, k) (((k) >> 6) * 10240u + SW128((uint32_t)(((m) << 7) | (((k) & 63) << 1))))

__device__ __forceinline__ void mask_rc(int k, int& r, int& c) {
    int base;
    if      (k < 80)  { r = 0; base = 0;   }
    else if (k < 159) { r = 1; base = 80;  }
    else if (k < 237) { r = 2; base = 159; }
    else if (k < 314) { r = 3; base = 237; }
    else if (k < 390) { r = 4; base = 314; }
    else              { r = 5; base = 390; }
    c = r + 1 + (k - base);
}

// ------------------------- PTX helpers --------------------------------------
__device__ __forceinline__ uint32_t s_u32(const void* p) {
    return (uint32_t)__cvta_generic_to_shared(p);
}
__device__ __forceinline__ void ldsm_x4(uint32_t* r, uint32_t addr) {
    asm volatile("ldmatrix.sync.aligned.m8n8.x4.shared.b16 {%0,%1,%2,%3}, [%4];"
        : "=r"(r[0]), "=r"(r[1]), "=r"(r[2]), "=r"(r[3]) : "r"(addr));
}
__device__ __forceinline__ void ldsm_x2(uint32_t* r, uint32_t addr) {
    asm volatile("ldmatrix.sync.aligned.m8n8.x2.shared.b16 {%0,%1}, [%2];"
        : "=r"(r[0]), "=r"(r[1]) : "r"(addr));
}
__device__ __forceinline__ void mma_bf16(float* d, const uint32_t* a, const uint32_t* b) {
    asm volatile("mma.sync.aligned.m16n8k16.row.col.f32.bf16.bf16.f32 "
        "{%0,%1,%2,%3}, {%4,%5,%6,%7}, {%8,%9}, {%0,%1,%2,%3};"
        : "+f"(d[0]), "+f"(d[1]), "+f"(d[2]), "+f"(d[3])
        : "r"(a[0]), "r"(a[1]), "r"(a[2]), "r"(a[3]), "r"(b[0]), "r"(b[1]));
}
__device__ __forceinline__ void bulkcp(uint32_t dst, const void* src, uint32_t bytes,
                                       uint32_t mbar) {
    asm volatile(
        "cp.async.bulk.shared::cluster.global.mbarrier::complete_tx::bytes [%0], [%1], %2, [%3];"
        :: "r"(dst), "l"(src), "r"(bytes), "r"(mbar) : "memory");
}
__device__ __forceinline__ void mbar_init(uint32_t mbar, uint32_t cnt) {
    asm volatile("mbarrier.init.shared.b64 [%0], %1;" :: "r"(mbar), "r"(cnt) : "memory");
}
__device__ __forceinline__ void mbar_expect(uint32_t mbar, uint32_t tx) {
    asm volatile("mbarrier.arrive.expect_tx.shared.b64 _, [%0], %1;"
                 :: "r"(mbar), "r"(tx) : "memory");
}
#define MWAIT(addr, ph) do { \
    uint32_t _d = 0; \
    while (!_d) { \
        asm volatile("{\n\t.reg .pred p;\n\t" \
            "mbarrier.try_wait.parity.acquire.cta.shared::cta.b64 p, [%1], %2;\n\t" \
            "selp.b32 %0, 1, 0, p;\n\t}" : "=r"(_d) : "r"(addr), "r"(ph)); \
    } } while (0)

// ---------------- replay-safe grid barrier (all NBLK blocks) ----------------
__device__ __forceinline__ void gsync() {
    __syncthreads();
    if (threadIdx.x == 0) {
        unsigned g0 = atomicAdd(&g_gen, 0u);   // stable: barrier can't finish w/o us
        __threadfence();
        unsigned a = atomicAdd(&g_cnt, 1u);
        if (a == NBLK - 1u) {
            atomicExch(&g_cnt, 0u);            // reset BEFORE releasing
            __threadfence();
            atomicAdd(&g_gen, 1u);
        } else {
            while (atomicAdd(&g_gen, 0u) == g0) __nanosleep(32);
        }
        __threadfence();
    }
    __syncthreads();
}

// --------- weight conversion to BLOCKED+SWIZZLED bf16 (separate launch) -----
#define T1 2097152
#define T2 16777216
#define T3 2097152
__global__ void k_convall(const float* s0, const float* s1, const float* s2,
                          const float* s3, const float* s4, const float* s5) {
    long long e = (long long)(blockIdx.x * 256 + threadIdx.x) * 8;
    const float* src; char* dst; long long local; int type;
    if      (e < T1)           { src = s0; dst = (char*)g_W1b[0]; local = e;                  type = 0; }
    else if (e < T1+T2)        { src = s1; dst = (char*)g_W2b[0]; local = e - T1;             type = 1; }
    else if (e < T1+T2+T3)     { src = s2; dst = (char*)g_W3b[0]; local = e - (T1+T2);        type = 2; }
    else if (e < 2*T1+T2+T3)   { src = s3; dst = (char*)g_W1b[1]; local = e - (T1+T2+T3);     type = 0; }
    else if (e < 2*T1+2*T2+T3) { src = s4; dst = (char*)g_W2b[1]; local = e - (2*T1+T2+T3);   type = 1; }
    else                       { src = s5; dst = (char*)g_W3b[1]; local = e - (2*T1+2*T2+T3); type = 2; }
    int K = (type == 0) ? 512 : 4096;
    int n = (int)(local / K);
    int k = (int)(local - (long long)n * K);
    float v[8];
    #pragma unroll
    for (int j = 0; j < 8; j++) {
        bool ok = (type == 0) ? (k + j < DIN) : (type == 2 ? (n < DIN) : true);
        int cols = (type == 0) ? DIN : 4096;
        v[j] = ok ? src[(size_t)n * cols + k + j] : 0.f;
    }
    uint32_t off = ((uint32_t)(n >> 5) * (uint32_t)(K >> 6) + (uint32_t)(k >> 6)) * 4096u
                 + SW128((uint32_t)(((n & 31) << 7) | ((k & 63) << 1)));
    uint32_t o[4];
    #pragma unroll
    for (int j = 0; j < 4; j++) {
        __nv_bfloat162 h;
        h.x = __float2bfloat16(v[2 * j]);
        h.y = __float2bfloat16(v[2 * j + 1]);
        o[j] = *(uint32_t*)&h;
    }
    *(uint4*)(dst + off) = make_uint4(o[0], o[1], o[2], o[3]);
}

// ------------- GEMM phase (device fn; all 128 blocks participate) -----------
// D[80 x 32] = A[80 x Kchunk] * W[32 x Kchunk]^T at (nb, splitK sk).
// stage = [A_kg0 10240][A_kg1 10240][W_kg0 4096][W_kg1 4096] = 28672B, 3 stages.
#define STB 28672
#define GSMEM (3 * STB + 1024)
__device__ __noinline__ void gemm_phase(
    const char* Ablk, const char* Wblk, int KbTotal, int Kchunk,
    const float* bias, void* Cout, int partStride, int nb, int sk, int mode,
    char* dalign, uint64_t* s_mbar)
{
    const int tid = threadIdx.x, w = tid >> 5, l = tid & 31;
    const int kg = w >> 2, nw = w & 3;
    const int k0 = sk * Kchunk;
    const int kgK = Kchunk >> 1;
    const int nIt = kgK >> 6;
    const uint32_t sbase = s_u32(dalign);

    if (tid == 0) {
        #pragma unroll
        for (int i = 0; i < 3; i++) mbar_init(s_u32(&s_mbar[i]), 1);
    }
    __syncthreads();

    auto issue = [&](int it, int s) {
        uint32_t st = sbase + s * STB;
        uint32_t mb = s_u32(&s_mbar[s]);
        int kb0 = (k0 >> 6) + it;
        int kb1 = ((k0 + kgK) >> 6) + it;
        mbar_expect(mb, STB);
        bulkcp(st,         Ablk + (size_t)kb0 * 10240, 10240, mb);
        bulkcp(st + 10240, Ablk + (size_t)kb1 * 10240, 10240, mb);
        bulkcp(st + 20480, Wblk + ((size_t)nb * KbTotal + kb0) * 4096, 4096, mb);
        bulkcp(st + 24576, Wblk + ((size_t)nb * KbTotal + kb1) * 4096, 4096, mb);
    };

    if (tid == 0) {
        asm volatile("fence.proxy.async;" ::: "memory");
        int npre = (nIt < 3) ? nIt : 3;
        for (int c = 0; c < npre; c++) issue(c, c);
    }

    float acc[5][4];
    #pragma unroll
    for (int mt = 0; mt < 5; mt++)
        #pragma unroll
        for (int q = 0; q < 4; q++) acc[mt][q] = 0.f;

    const int arow = (l & 7) + 8 * ((l >> 3) & 1);
    const int acolB = 16 * (l >> 4);
    const int brow = (l & 7);
    const int bcolB = 16 * ((l >> 3) & 1);

    int ph[3] = {0, 0, 0};
    for (int it = 0; it < nIt; it++) {
        int s = it % 3;
        MWAIT(s_u32(&s_mbar[s]), ph[s]); ph[s] ^= 1;
        uint32_t A0 = sbase + s * STB + kg * 10240;
        uint32_t W0 = sbase + s * STB + 20480 + kg * 4096;
        #pragma unroll
        for (int ks = 0; ks < 4; ks++) {
            uint32_t kb = ks * 32;
            uint32_t b[2];
            ldsm_x2(b, W0 + SW128((uint32_t)((nw * 8 + brow) * 128) + kb + bcolB));
            #pragma unroll
            for (int mt = 0; mt < 5; mt++) {
                uint32_t a[4];
                ldsm_x4(a, A0 + SW128((uint32_t)((mt * 16 + arow) * 128) + kb + acolB));
                mma_bf16(acc[mt], a, b);
            }
        }
        __syncthreads();
        if (tid == 0 && it + 3 < nIt) issue(it + 3, s);
    }

    float* scr = (float*)dalign;
    __syncthreads();
    if (kg == 1) {
        #pragma unroll
        for (int mt = 0; mt < 5; mt++)
            #pragma unroll
            for (int q = 0; q < 4; q++)
                scr[((nw * 5 + mt) * 32 + l) * 4 + q] = acc[mt][q];
    }
    __syncthreads();
    if (kg == 0) {
        int n = nb * 32 + nw * 8 + 2 * (l & 3);
        #pragma unroll
        for (int mt = 0; mt < 5; mt++) {
            float v[4];
            #pragma unroll
            for (int q = 0; q < 4; q++)
                v[q] = acc[mt][q] + scr[((nw * 5 + mt) * 32 + l) * 4 + q];
            int m0 = mt * 16 + (l >> 2);
            if (mode == 0) {
                char* H = (char*)Cout;
                float b0 = bias[n], b1 = bias[n + 1];
                __nv_bfloat162 h0, h1;
                h0.x = __float2bfloat16(fmaxf(v[0] + b0, 0.f));
                h0.y = __float2bfloat16(fmaxf(v[1] + b1, 0.f));
                h1.x = __float2bfloat16(fmaxf(v[2] + b0, 0.f));
                h1.y = __float2bfloat16(fmaxf(v[3] + b1, 0.f));
                *(__nv_bfloat162*)(H + ABLK_OFF(m0, n))     = h0;
                *(__nv_bfloat162*)(H + ABLK_OFF(m0 + 8, n)) = h1;
            } else {
                float* Cp = (float*)Cout + (size_t)sk * partStride;
                *(float2*)&Cp[(size_t)m0 * KPAD + n]       = make_float2(v[0], v[1]);
                *(float2*)&Cp[(size_t)(m0 + 8) * KPAD + n] = make_float2(v[2], v[3]);
            }
        }
    }
    __syncthreads();
}

// ------------------------------- mega kernel --------------------------------
struct MegaP {
    const float *fs, *fq, *scale;
    const float *b1[2], *b2[2], *b3[2];
    float* out;
};

__global__ void __launch_bounds__(NT, 1) k_mega(MegaP P) {
    extern __shared__ char dyn[];
    __shared__ float s_srow[6 * NN];
    __shared__ int   s_a[81];
    __shared__ float s_red[NT];
    __shared__ float s_Gp[NN];
    __shared__ uint64_t s_mbar[3];
    char* dalign = (char*)(((uintptr_t)dyn + 1023ull) & ~1023ull);
    const int b = blockIdx.x;
    const int tid = threadIdx.x;
    const int w = tid >> 5, l = tid & 31;

    // phase: init (supp mean + query copy), striped over whole grid
    for (int idx = b * NT + tid; idx < NN * FEAT; idx += NBLK * NT) {
        int r = idx / FEAT, d = idx % FEAT;
        if (r < NCLS) {
            float s = 0.f;
            #pragma unroll
            for (int sh = 0; sh < 5; sh++) s += P.fs[(r * 5 + sh) * FEAT + d];
            g_supp[r * FEAT + d] = s / 5.0f;
        } else {
            g_query[(r - NCLS) * FEAT + d] = P.fq[(r - NCLS) * FEAT + d];
        }
    }
    gsync();

    // phase: initial norms + F for all rows
    if (b < NN) {
        const float* src = (b < NCLS) ? (g_supp + b * FEAT) : (g_query + (b - NCLS) * FEAT);
        float s = 0.f;
        for (int d = tid; d < FEAT; d += NT) { float v = src[d]; s += v * v; }
        s_red[tid] = s; __syncthreads();
        for (int o = 128; o > 0; o >>= 1) { if (tid < o) s_red[tid] += s_red[tid + o]; __syncthreads(); }
        float nrm = fmaxf(sqrtf(s_red[0]), 1e-12f);
        if (tid == 0) g_nrm[b] = nrm;
        float inv = 1.f / nrm;
        for (int d = tid; d < FEAT; d += NT) g_F[b * FEAT + d] = src[d] * inv;
    }
    gsync();

    for (int step = 0; step < 3; step++) {
        for (int br = 0; br < 2; br++) {
            // ---- simsort: 6 sim rows from g_F, rank sort, gather, zero G ----
            if (b < NN) {
                float* sF = (float*)dalign;   // 6 x 640 floats
                for (int t = tid; t < 6 * FEAT; t += NT) {
                    int rr = t / FEAT, d = t - rr * FEAT;
                    int row = (rr == 0) ? b : (rr - 1);
                    sF[t] = g_F[row * FEAT + d];
                }
                if (tid == 0) s_a[0] = b;
                __syncthreads();
                for (int j = w; j < NN; j += 8) {
                    float acc[6] = {0.f, 0.f, 0.f, 0.f, 0.f, 0.f};
                    for (int d = l; d < FEAT; d += 32) {
                        float fj = g_F[j * FEAT + d];
                        #pragma unroll
                        for (int rr = 0; rr < 6; rr++) acc[rr] += sF[rr * FEAT + d] * fj;
                    }
                    #pragma unroll
                    for (int rr = 0; rr < 6; rr++) {
                        #pragma unroll
                        for (int o = 16; o > 0; o >>= 1)
                            acc[rr] += __shfl_xor_sync(0xffffffffu, acc[rr], o);
                    }
                    if (l == 0) {
                        #pragma unroll
                        for (int rr = 0; rr < 6; rr++) s_srow[rr * NN + j] = acc[rr];
                    }
                }
                __syncthreads();
                if (tid < NCLS) {   // stable-descending rank over row i, cols 0..4
                    float v = s_srow[tid];
                    int rank = 0;
                    #pragma unroll
                    for (int j = 0; j < NCLS; j++) {
                        float u = s_srow[j];
                        if (j != tid && (u > v || (u == v && j < tid))) rank++;
                    }
                    s_a[1 + rank] = tid;
                }
                if (tid < NQ) {     // cols 5..79
                    float v = s_srow[NCLS + tid];
                    int rank = 0;
                    for (int j = 0; j < NQ; j++) {
                        float u = s_srow[NCLS + j];
                        if (u > v || (u == v && j < tid)) rank++;
                    }
                    s_a[6 + rank] = NCLS + tid;
                }
                __syncthreads();
                for (int t = tid; t < 81; t += NT) g_idx[b * 81 + t] = s_a[t];
                char* xb = (char*)g_xb;
                for (int k = tid; k < KPAD; k += NT) {
                    float v = 0.f;
                    if (k < DIN) {
                        int r, c; mask_rc(k, r, c);
                        int ar = s_a[r];
                        int rrow = (r == 0) ? 0 : (1 + ar);
                        v = s_srow[rrow * NN + s_a[c]];
                    }
                    *(__nv_bfloat16*)(xb + ABLK_OFF(b, k)) = __float2bfloat16(v);
                }
                for (int t = tid; t < NN; t += NT) g_G[b * NN + t] = 0.f;
            }
            gsync();

            // ---- GEMMs ----
            gemm_phase((const char*)g_xb,  (const char*)g_W1b[br], 8,  512,
                       P.b1[br], g_h1b, 0, b, 0, 0, dalign, s_mbar);
            gsync();
            gemm_phase((const char*)g_h1b, (const char*)g_W2b[br], 64, 4096,
                       P.b2[br], g_h2b, 0, b, 0, 0, dalign, s_mbar);
            gsync();
            gemm_phase((const char*)g_h2b, (const char*)g_W3b[br], 64, 512,
                       nullptr, g_parts, NN * KPAD, b & 15, b >> 4, 1, dalign, s_mbar);
            gsync();

            // ---- scatter: G += g at (a_r,a_c),(a_c,a_r); g = sum8 + b3 ----
            if (b < NN) {
                for (int t = tid; t < 81; t += NT) s_a[t] = g_idx[b * 81 + t];
                __syncthreads();
                const float* b3 = P.b3[br];
                for (int k = tid; k < DIN; k += NT) {
                    float v = b3[k];
                    #pragma unroll
                    for (int s = 0; s < 8; s++) v += g_parts[(size_t)s * NN * KPAD + b * KPAD + k];
                    int r, c; mask_rc(k, r, c);
                    atomicAdd(&g_G[s_a[r] * NN + s_a[c]], v);
                    atomicAdd(&g_G[s_a[c] * NN + s_a[r]], v);
                }
            }
            gsync();

            // ---- update: Fbar = G_p F; normalize-VJP; SGD on raw row ----
            int nrows = br ? NQ : NCLS;
            int lo = br ? NCLS : 0;
            float* target = br ? g_query : g_supp;
            if (b < nrows) {
                int p = lo + b;
                float* fb = (float*)dalign;   // 640 floats
                for (int q = tid; q < NN; q += NT) s_Gp[q] = g_G[p * NN + q];
                __syncthreads();
                for (int d = tid; d < FEAT; d += NT) {
                    float s = 0.f;
                    #pragma unroll 8
                    for (int q = 0; q < NN; q++) s += s_Gp[q] * g_F[q * FEAT + d];
                    fb[d] = s;
                }
                __syncthreads();
                float part = 0.f;
                for (int d = tid; d < FEAT; d += NT) part += fb[d] * g_F[p * FEAT + d];
                s_red[tid] = part; __syncthreads();
                for (int o = 128; o > 0; o >>= 1) { if (tid < o) s_red[tid] += s_red[tid + o]; __syncthreads(); }
                float dot = s_red[0];
                float inv = 1.f / g_nrm[p];
                for (int d = tid; d < FEAT; d += NT) {
                    float fp = g_F[p * FEAT + d];
                    float dX = (fb[d] - dot * fp) * inv;
                    target[(p - lo) * FEAT + d] -= LRC * dX;
                }
            }
            gsync();

            // ---- renorm changed rows -> g_F, g_nrm ----
            if (b < nrows) {
                int p = lo + b;
                const float* src = target + (p - lo) * FEAT;
                float s = 0.f;
                for (int d = tid; d < FEAT; d += NT) { float v = src[d]; s += v * v; }
                s_red[tid] = s; __syncthreads();
                for (int o = 128; o > 0; o >>= 1) { if (tid < o) s_red[tid] += s_red[tid + o]; __syncthreads(); }
                float nrm = fmaxf(sqrtf(s_red[0]), 1e-12f);
                if (tid == 0) g_nrm[p] = nrm;
                float inv = 1.f / nrm;
                for (int d = tid; d < FEAT; d += NT) g_F[p * FEAT + d] = src[d] * inv;
            }
            gsync();
        }
    }

    // ---- final: out[q][w] = dot(F_w, F_{5+q}) * scale ----
    if (b < NQ) {
        if (w < NCLS) {
            float p = 0.f;
            const float* Fq = g_F + (NCLS + b) * FEAT;
            const float* Fs = g_F + w * FEAT;
            for (int d = l; d < FEAT; d += 32) p += Fs[d] * Fq[d];
            #pragma unroll
            for (int o = 16; o > 0; o >>= 1) p += __shfl_xor_sync(0xffffffffu, p, o);
            if (l == 0) P.out[b * NCLS + w] = p * P.scale[0];
        }
    }
}

// ----------------------------------------------------------------------------
extern "C" void kernel_launch(void* const* d_in, const int* in_sizes, int n_in,
                              void* d_out, int out_size) {
    k_convall<<<20480, 256>>>(
        (const float*)d_in[3],  (const float*)d_in[5],  (const float*)d_in[7],
        (const float*)d_in[9],  (const float*)d_in[11], (const float*)d_in[13]);

    MegaP P;
    P.fs    = (const float*)d_in[0];
    P.fq    = (const float*)d_in[1];
    P.scale = (const float*)d_in[2];
    P.b1[0] = (const float*)d_in[4];   P.b1[1] = (const float*)d_in[10];
    P.b2[0] = (const float*)d_in[6];   P.b2[1] = (const float*)d_in[12];
    P.b3[0] = (const float*)d_in[8];   P.b3[1] = (const float*)d_in[14];
    P.out   = (float*)d_out;

    cudaFuncSetAttribute(k_mega, cudaFuncAttributeMaxDynamicSharedMemorySize, GSMEM);
    k_mega<<<NBLK, NT, GSMEM>>>(P);
}

// round 7
// speedup vs baseline: 1.1425x; 1.1425x over previous
#include <cuda_runtime.h>
#include <cuda_bf16.h>
#include <math.h>
#include <stdint.h>

#define NCLS 5
#define NQ   75
#define NN   80
#define FEAT 640
#define HID  4096
#define DIN  465
#define KPAD 512
#define LRC  1e-3f

// ------------------------- scratch (device globals) -------------------------
__device__ __align__(128) float g_supp[NCLS * FEAT];
__device__ __align__(128) float g_query[NQ * FEAT];
__device__ __align__(128) float g_F[NN * FEAT];       // normalized rows
__device__ __align__(128) float g_Fold[NQ * FEAT];    // snapshot of changing rows
__device__ float g_nrm[NN];
__device__ int   g_idx[NN * 81];
__device__ __align__(128) float g_G[NN * NN];
__device__ __align__(128) float g_parts[8 * NN * KPAD];
// activations, BLOCKED: A_blk[kb][80][64] bf16, SW128-swizzled 128B rows
__device__ __align__(1024) __nv_bfloat16 g_xb [NN * KPAD];
__device__ __align__(1024) __nv_bfloat16 g_h1b[NN * HID];
__device__ __align__(1024) __nv_bfloat16 g_h2b[NN * HID];
// weights, BLOCKED: W_blk[nb][kb][32][64] bf16, SW128-swizzled
__device__ __align__(1024) __nv_bfloat16 g_W1b[2][HID * KPAD];
__device__ __align__(1024) __nv_bfloat16 g_W2b[2][HID * HID];
__device__ __align__(1024) __nv_bfloat16 g_W3b[2][KPAD * HID];

#define SW128(o) ((o) ^ (((o) >> 3) & 0x70))
#define ABLK_OFF(m, k) (((k) >> 6) * 10240u + SW128((uint32_t)(((m) << 7) | (((k) & 63) << 1))))

__device__ __forceinline__ void mask_rc(int k, int& r, int& c) {
    int base;
    if      (k < 80)  { r = 0; base = 0;   }
    else if (k < 159) { r = 1; base = 80;  }
    else if (k < 237) { r = 2; base = 159; }
    else if (k < 314) { r = 3; base = 237; }
    else if (k < 390) { r = 4; base = 314; }
    else              { r = 5; base = 390; }
    c = r + 1 + (k - base);
}

// ------------------------- PTX helpers --------------------------------------
__device__ __forceinline__ uint32_t s_u32(const void* p) {
    return (uint32_t)__cvta_generic_to_shared(p);
}
__device__ __forceinline__ void ldsm_x4(uint32_t* r, uint32_t addr) {
    asm volatile("ldmatrix.sync.aligned.m8n8.x4.shared.b16 {%0,%1,%2,%3}, [%4];"
        : "=r"(r[0]), "=r"(r[1]), "=r"(r[2]), "=r"(r[3]) : "r"(addr));
}
__device__ __forceinline__ void ldsm_x2(uint32_t* r, uint32_t addr) {
    asm volatile("ldmatrix.sync.aligned.m8n8.x2.shared.b16 {%0,%1}, [%2];"
        : "=r"(r[0]), "=r"(r[1]) : "r"(addr));
}
__device__ __forceinline__ void mma_bf16(float* d, const uint32_t* a, const uint32_t* b) {
    asm volatile("mma.sync.aligned.m16n8k16.row.col.f32.bf16.bf16.f32 "
        "{%0,%1,%2,%3}, {%4,%5,%6,%7}, {%8,%9}, {%0,%1,%2,%3};"
        : "+f"(d[0]), "+f"(d[1]), "+f"(d[2]), "+f"(d[3])
        : "r"(a[0]), "r"(a[1]), "r"(a[2]), "r"(a[3]), "r"(b[0]), "r"(b[1]));
}
__device__ __forceinline__ void bulkcp(uint32_t dst, const void* src, uint32_t bytes,
                                       uint32_t mbar) {
    asm volatile(
        "cp.async.bulk.shared::cluster.global.mbarrier::complete_tx::bytes [%0], [%1], %2, [%3];"
        :: "r"(dst), "l"(src), "r"(bytes), "r"(mbar) : "memory");
}
__device__ __forceinline__ void mbar_init(uint32_t mbar, uint32_t cnt) {
    asm volatile("mbarrier.init.shared.b64 [%0], %1;" :: "r"(mbar), "r"(cnt) : "memory");
}
__device__ __forceinline__ void mbar_expect(uint32_t mbar, uint32_t tx) {
    asm volatile("mbarrier.arrive.expect_tx.shared.b64 _, [%0], %1;"
                 :: "r"(mbar), "r"(tx) : "memory");
}
#define MWAIT(addr, ph) do { \
    uint32_t _d = 0; \
    while (!_d) { \
        asm volatile("{\n\t.reg .pred p;\n\t" \
            "mbarrier.try_wait.parity.acquire.cta.shared::cta.b64 p, [%1], %2;\n\t" \
            "selp.b32 %0, 1, 0, p;\n\t}" : "=r"(_d) : "r"(addr), "r"(ph)); \
    } } while (0)

// --------- weight conversion to BLOCKED+SWIZZLED bf16 -----------------------
#define T1 2097152
#define T2 16777216
#define T3 2097152
__global__ void k_convall(const float* s0, const float* s1, const float* s2,
                          const float* s3, const float* s4, const float* s5) {
    long long e = (long long)(blockIdx.x * 256 + threadIdx.x) * 8;
    const float* src; char* dst; long long local; int type;
    if      (e < T1)           { src = s0; dst = (char*)g_W1b[0]; local = e;                  type = 0; }
    else if (e < T1+T2)        { src = s1; dst = (char*)g_W2b[0]; local = e - T1;             type = 1; }
    else if (e < T1+T2+T3)     { src = s2; dst = (char*)g_W3b[0]; local = e - (T1+T2);        type = 2; }
    else if (e < 2*T1+T2+T3)   { src = s3; dst = (char*)g_W1b[1]; local = e - (T1+T2+T3);     type = 0; }
    else if (e < 2*T1+2*T2+T3) { src = s4; dst = (char*)g_W2b[1]; local = e - (2*T1+T2+T3);   type = 1; }
    else                       { src = s5; dst = (char*)g_W3b[1]; local = e - (2*T1+2*T2+T3); type = 2; }
    int K = (type == 0) ? 512 : 4096;
    int n = (int)(local / K);
    int k = (int)(local - (long long)n * K);
    float v[8];
    #pragma unroll
    for (int j = 0; j < 8; j++) {
        bool ok = (type == 0) ? (k + j < DIN) : (type == 2 ? (n < DIN) : true);
        int cols = (type == 0) ? DIN : 4096;
        v[j] = ok ? src[(size_t)n * cols + k + j] : 0.f;
    }
    uint32_t off = ((uint32_t)(n >> 5) * (uint32_t)(K >> 6) + (uint32_t)(k >> 6)) * 4096u
                 + SW128((uint32_t)(((n & 31) << 7) | ((k & 63) << 1)));
    uint32_t o[4];
    #pragma unroll
    for (int j = 0; j < 4; j++) {
        __nv_bfloat162 h;
        h.x = __float2bfloat16(v[2 * j]);
        h.y = __float2bfloat16(v[2 * j + 1]);
        o[j] = *(uint32_t*)&h;
    }
    *(uint4*)(dst + off) = make_uint4(o[0], o[1], o[2], o[3]);
}

// -------- init: build raw rows (supp mean / query copy) + norm + F ----------
__global__ void k_initnorm(const float* __restrict__ fs, const float* __restrict__ fq) {
    int i = blockIdx.x;              // 80 blocks x 256
    int tid = threadIdx.x;
    __shared__ float row[FEAT];
    __shared__ float red[256];
    float s = 0.f;
    if (i < NCLS) {
        for (int d = tid; d < FEAT; d += 256) {
            float v = 0.f;
            #pragma unroll
            for (int sh = 0; sh < 5; sh++) v += fs[(i * 5 + sh) * FEAT + d];
            v *= 0.2f;
            g_supp[i * FEAT + d] = v;
            row[d] = v; s += v * v;
        }
    } else {
        int q = i - NCLS;
        for (int d = tid; d < FEAT; d += 256) {
            float v = fq[q * FEAT + d];
            g_query[q * FEAT + d] = v;
            row[d] = v; s += v * v;
        }
    }
    red[tid] = s; __syncthreads();
    for (int o = 128; o > 0; o >>= 1) { if (tid < o) red[tid] += red[tid + o]; __syncthreads(); }
    float nrm = fmaxf(sqrtf(red[0]), 1e-12f);
    if (tid == 0) g_nrm[i] = nrm;
    float inv = 1.f / nrm;
    for (int d = tid; d < FEAT; d += 256) g_F[i * FEAT + d] = row[d] * inv;
}

// ----- simsort: 6 needed sim rows from g_F + rank sort + gather + zero G ----
__global__ void k_simsort() {
    int i = blockIdx.x;              // 80 blocks x 256
    int tid = threadIdx.x;
    int w = tid >> 5, l = tid & 31;
    __shared__ float sF[6 * FEAT];   // row 0 = i, rows 1..5 = supp 0..4
    __shared__ float srow[6 * NN];
    __shared__ int a[81];
    for (int t = tid; t < 6 * FEAT; t += 256) {
        int rr = t / FEAT, d = t - rr * FEAT;
        int row = (rr == 0) ? i : (rr - 1);
        sF[t] = g_F[row * FEAT + d];
    }
    if (tid == 0) a[0] = i;
    __syncthreads();
    for (int j = w; j < NN; j += 8) {
        float acc[6] = {0.f, 0.f, 0.f, 0.f, 0.f, 0.f};
        const float* Fj = g_F + j * FEAT;
        for (int d = l; d < FEAT; d += 32) {
            float fj = Fj[d];
            #pragma unroll
            for (int rr = 0; rr < 6; rr++) acc[rr] += sF[rr * FEAT + d] * fj;
        }
        #pragma unroll
        for (int rr = 0; rr < 6; rr++) {
            #pragma unroll
            for (int o = 16; o > 0; o >>= 1)
                acc[rr] += __shfl_xor_sync(0xffffffffu, acc[rr], o);
        }
        if (l == 0) {
            #pragma unroll
            for (int rr = 0; rr < 6; rr++) srow[rr * NN + j] = acc[rr];
        }
    }
    __syncthreads();
    if (tid < NCLS) {                 // stable-descending rank, support keys
        float v = srow[tid];
        int rank = 0;
        #pragma unroll
        for (int j = 0; j < NCLS; j++) {
            float u = srow[j];
            if (j != tid && (u > v || (u == v && j < tid))) rank++;
        }
        a[1 + rank] = tid;
    }
    if (tid < NQ) {                   // query keys
        float v = srow[NCLS + tid];
        int rank = 0;
        for (int j = 0; j < NQ; j++) {
            float u = srow[NCLS + j];
            if (u > v || (u == v && j < tid)) rank++;
        }
        a[6 + rank] = NCLS + tid;
    }
    __syncthreads();
    for (int t = tid; t < 81; t += 256) g_idx[i * 81 + t] = a[t];
    char* xb = (char*)g_xb;
    for (int k = tid; k < KPAD; k += 256) {
        float v = 0.f;
        if (k < DIN) {
            int r, c; mask_rc(k, r, c);
            int rrow = (r == 0) ? 0 : (1 + a[r]);
            v = srow[rrow * NN + a[c]];
        }
        *(__nv_bfloat16*)(xb + ABLK_OFF(i, k)) = __float2bfloat16(v);
    }
    for (int t = tid; t < NN; t += 256) g_G[i * NN + t] = 0.f;
}

// ============ bulk-loaded mma.sync GEMM (BN=32, 2 warp-kgroups) =============
#define STB 28672
#define GSMEM (3 * STB + 1024)
template<int MODE>
__global__ void __launch_bounds__(256) k_gemmB(
    const char* __restrict__ Ablk, const char* __restrict__ Wblk,
    int KbTotal, int Kchunk, const float* __restrict__ bias,
    void* __restrict__ Cout, int partStride)
{
    extern __shared__ char dyn[];
    __shared__ uint64_t mbar[3];
    const int tid = threadIdx.x, w = tid >> 5, l = tid & 31;
    const int kg = w >> 2, nw = w & 3;
    const int nb = blockIdx.x;
    const int k0 = blockIdx.y * Kchunk;
    const int kgK = Kchunk >> 1;
    const int nIt = kgK >> 6;
    const uint32_t sbase = (s_u32(dyn) + 1023u) & ~1023u;
    char* dalign = (char*)(((uintptr_t)dyn + 1023ull) & ~1023ull);

    if (tid == 0) {
        #pragma unroll
        for (int i = 0; i < 3; i++) mbar_init(s_u32(&mbar[i]), 1);
    }
    __syncthreads();

    auto issue = [&](int it, int s) {
        uint32_t st = sbase + s * STB;
        uint32_t mb = s_u32(&mbar[s]);
        int kb0 = (k0 >> 6) + it;
        int kb1 = ((k0 + kgK) >> 6) + it;
        mbar_expect(mb, STB);
        bulkcp(st,         Ablk + (size_t)kb0 * 10240, 10240, mb);
        bulkcp(st + 10240, Ablk + (size_t)kb1 * 10240, 10240, mb);
        bulkcp(st + 20480, Wblk + ((size_t)nb * KbTotal + kb0) * 4096, 4096, mb);
        bulkcp(st + 24576, Wblk + ((size_t)nb * KbTotal + kb1) * 4096, 4096, mb);
    };

    if (tid == 0) {
        int npre = (nIt < 3) ? nIt : 3;
        for (int c = 0; c < npre; c++) issue(c, c);
    }

    float acc[5][4];
    #pragma unroll
    for (int mt = 0; mt < 5; mt++)
        #pragma unroll
        for (int q = 0; q < 4; q++) acc[mt][q] = 0.f;

    const int arow = (l & 7) + 8 * ((l >> 3) & 1);
    const int acolB = 16 * (l >> 4);
    const int brow = (l & 7);
    const int bcolB = 16 * ((l >> 3) & 1);

    int ph[3] = {0, 0, 0};
    for (int it = 0; it < nIt; it++) {
        int s = it % 3;
        MWAIT(s_u32(&mbar[s]), ph[s]); ph[s] ^= 1;
        uint32_t A0 = sbase + s * STB + kg * 10240;
        uint32_t W0 = sbase + s * STB + 20480 + kg * 4096;
        #pragma unroll
        for (int ks = 0; ks < 4; ks++) {
            uint32_t kb = ks * 32;
            uint32_t b[2];
            ldsm_x2(b, W0 + SW128((uint32_t)((nw * 8 + brow) * 128) + kb + bcolB));
            #pragma unroll
            for (int mt = 0; mt < 5; mt++) {
                uint32_t a[4];
                ldsm_x4(a, A0 + SW128((uint32_t)((mt * 16 + arow) * 128) + kb + acolB));
                mma_bf16(acc[mt], a, b);
            }
        }
        __syncthreads();
        if (tid == 0 && it + 3 < nIt) issue(it + 3, s);
    }

    float* scr = (float*)dalign;
    __syncthreads();
    if (kg == 1) {
        #pragma unroll
        for (int mt = 0; mt < 5; mt++)
            #pragma unroll
            for (int q = 0; q < 4; q++)
                scr[((nw * 5 + mt) * 32 + l) * 4 + q] = acc[mt][q];
    }
    __syncthreads();
    if (kg == 0) {
        int n = nb * 32 + nw * 8 + 2 * (l & 3);
        #pragma unroll
        for (int mt = 0; mt < 5; mt++) {
            float v[4];
            #pragma unroll
            for (int q = 0; q < 4; q++)
                v[q] = acc[mt][q] + scr[((nw * 5 + mt) * 32 + l) * 4 + q];
            int m0 = mt * 16 + (l >> 2);
            if (MODE == 0) {
                char* H = (char*)Cout;
                float b0 = bias[n], b1 = bias[n + 1];
                __nv_bfloat162 h0, h1;
                h0.x = __float2bfloat16(fmaxf(v[0] + b0, 0.f));
                h0.y = __float2bfloat16(fmaxf(v[1] + b1, 0.f));
                h1.x = __float2bfloat16(fmaxf(v[2] + b0, 0.f));
                h1.y = __float2bfloat16(fmaxf(v[3] + b1, 0.f));
                *(__nv_bfloat162*)(H + ABLK_OFF(m0, n))     = h0;
                *(__nv_bfloat162*)(H + ABLK_OFF(m0 + 8, n)) = h1;
            } else {
                float* Cp = (float*)Cout + (size_t)blockIdx.y * partStride;
                *(float2*)&Cp[(size_t)m0 * KPAD + n]       = make_float2(v[0], v[1]);
                *(float2*)&Cp[(size_t)(m0 + 8) * KPAD + n] = make_float2(v[2], v[3]);
            }
        }
    }
}

// ------ scatter: G += g at (a_r,a_c),(a_c,a_r)  +  snapshot changing F rows -
__global__ void k_scatter(const float* __restrict__ b3, int lo, int nrows) {
    int i = blockIdx.x;              // 80 blocks x 128
    int tid = threadIdx.x;
    __shared__ int a[81];
    for (int t = tid; t < 81; t += 128) a[t] = g_idx[i * 81 + t];
    __syncthreads();
    for (int k = tid; k < DIN; k += 128) {
        float v = b3[k];
        #pragma unroll
        for (int s = 0; s < 8; s++) v += g_parts[(size_t)s * NN * KPAD + i * KPAD + k];
        int r, c; mask_rc(k, r, c);
        atomicAdd(&g_G[a[r] * NN + a[c]], v);
        atomicAdd(&g_G[a[c] * NN + a[r]], v);
    }
    // snapshot g_F rows [lo, lo+nrows) -> g_Fold (read by next k_update)
    for (int t = i * 128 + tid; t < nrows * FEAT; t += NN * 128)
        g_Fold[t] = g_F[lo * FEAT + t];
}

// --- update: Fbar = Gbar_p F (pre-update F via snapshot); VJP; SGD; renorm --
__global__ void k_update(int lo, int nrows, float* __restrict__ target) {
    int p = lo + blockIdx.x;         // nrows blocks x 256
    int tid = threadIdx.x;
    __shared__ float Gp[NN];
    __shared__ float fb[FEAT];
    __shared__ float red[256];
    __shared__ const float* rp[NN];
    for (int q = tid; q < NN; q += 256) {
        Gp[q] = g_G[p * NN + q];
        rp[q] = (q >= lo && q < lo + nrows) ? (g_Fold + (q - lo) * FEAT) : (g_F + q * FEAT);
    }
    __syncthreads();
    for (int d = tid; d < FEAT; d += 256) {
        float s = 0.f;
        #pragma unroll 8
        for (int q = 0; q < NN; q++) s += Gp[q] * rp[q][d];
        fb[d] = s;
    }
    __syncthreads();
    const float* fpold = g_Fold + (p - lo) * FEAT;
    float part = 0.f;
    for (int d = tid; d < FEAT; d += 256) part += fb[d] * fpold[d];
    red[tid] = part; __syncthreads();
    for (int o = 128; o > 0; o >>= 1) { if (tid < o) red[tid] += red[tid + o]; __syncthreads(); }
    float dot = red[0];
    float inv = 1.f / g_nrm[p];
    // apply SGD to raw row; stash new values in fb; accumulate new sumsq
    float s2 = 0.f;
    for (int d = tid; d < FEAT; d += 256) {
        float fp = fpold[d];
        float dX = (fb[d] - dot * fp) * inv;
        float nv = target[(p - lo) * FEAT + d] - LRC * dX;
        target[(p - lo) * FEAT + d] = nv;
        fb[d] = nv;
        s2 += nv * nv;
    }
    __syncthreads();
    red[tid] = s2; __syncthreads();
    for (int o = 128; o > 0; o >>= 1) { if (tid < o) red[tid] += red[tid + o]; __syncthreads(); }
    float nrm = fmaxf(sqrtf(red[0]), 1e-12f);
    if (tid == 0) g_nrm[p] = nrm;
    float invn = 1.f / nrm;
    for (int d = tid; d < FEAT; d += 256) g_F[p * FEAT + d] = fb[d] * invn;
}

// ------------- final: out[q][s] = dot(F_s, F_{5+q}) * scale -----------------
__global__ void k_final(const float* __restrict__ scale, float* __restrict__ out) {
    int q = blockIdx.x;              // 75 blocks x 256
    int tid = threadIdx.x;
    __shared__ float Fq[FEAT];
    for (int d = tid; d < FEAT; d += 256) Fq[d] = g_F[(NCLS + q) * FEAT + d];
    __syncthreads();
    int w = tid >> 5, l = tid & 31;
    if (w < NCLS) {
        const float* Fs = g_F + w * FEAT;
        float p = 0.f;
        for (int d = l; d < FEAT; d += 32) p += Fs[d] * Fq[d];
        #pragma unroll
        for (int o = 16; o > 0; o >>= 1) p += __shfl_xor_sync(0xffffffffu, p, o);
        if (l == 0) out[q * NCLS + w] = p * scale[0];
    }
}

// ----------------------------------------------------------------------------
extern "C" void kernel_launch(void* const* d_in, const int* in_sizes, int n_in,
                              void* d_out, int out_size) {
    const float* fs    = (const float*)d_in[0];
    const float* fq    = (const float*)d_in[1];
    const float* scale = (const float*)d_in[2];

    float *pp, *ps, *pq;
    char *pxb, *ph1b, *ph2b, *pw1b, *pw2b, *pw3b;
    cudaGetSymbolAddress((void**)&pp,   g_parts);
    cudaGetSymbolAddress((void**)&ps,   g_supp);
    cudaGetSymbolAddress((void**)&pq,   g_query);
    cudaGetSymbolAddress((void**)&pxb,  g_xb);
    cudaGetSymbolAddress((void**)&ph1b, g_h1b);
    cudaGetSymbolAddress((void**)&ph2b, g_h2b);
    cudaGetSymbolAddress((void**)&pw1b, g_W1b);
    cudaGetSymbolAddress((void**)&pw2b, g_W2b);
    cudaGetSymbolAddress((void**)&pw3b, g_W3b);

    cudaFuncSetAttribute(k_gemmB<0>, cudaFuncAttributeMaxDynamicSharedMemorySize, GSMEM);
    cudaFuncSetAttribute(k_gemmB<1>, cudaFuncAttributeMaxDynamicSharedMemorySize, GSMEM);

    k_convall<<<20480, 256>>>(
        (const float*)d_in[3],  (const float*)d_in[5],  (const float*)d_in[7],
        (const float*)d_in[9],  (const float*)d_in[11], (const float*)d_in[13]);
    k_initnorm<<<NN, 256>>>(fs, fq);

    for (int step = 0; step < 3; step++) {
        for (int br = 0; br < 2; br++) {
            const float* b1 = (const float*)d_in[3 + 6 * br + 1];
            const float* b2 = (const float*)d_in[3 + 6 * br + 3];
            const float* b3 = (const float*)d_in[3 + 6 * br + 5];
            char* W1b = pw1b + (size_t)br * T1 * 2;
            char* W2b = pw2b + (size_t)br * T2 * 2;
            char* W3b = pw3b + (size_t)br * T3 * 2;
            int lo    = br ? NCLS : 0;
            int nrows = br ? NQ : NCLS;
            float* target = br ? pq : ps;

            k_simsort<<<NN, 256>>>();
            k_gemmB<0><<<dim3(128, 1), 256, GSMEM>>>(pxb, W1b, 8, 512, b1, ph1b, 0);
            k_gemmB<0><<<dim3(128, 1), 256, GSMEM>>>(ph1b, W2b, 64, 4096, b2, ph2b, 0);
            k_gemmB<1><<<dim3(16, 8), 256, GSMEM>>>(ph2b, W3b, 64, 512, nullptr, pp, NN * KPAD);
            k_scatter<<<NN, 128>>>(b3, lo, nrows);
            k_update<<<nrows, 256>>>(lo, nrows, target);
        }
    }

    k_final<<<NQ, 256>>>(scale, (float*)d_out);
}

// round 8
// speedup vs baseline: 1.3195x; 1.1549x over previous
#include <cuda_runtime.h>
#include <cuda_bf16.h>
#include <math.h>
#include <stdint.h>

#define NCLS 5
#define NQ   75
#define NN   80
#define FEAT 640
#define HID  4096
#define DIN  465
#define KPAD 512
#define LRC  1e-3f

// ------------------------- scratch (device globals) -------------------------
__device__ __align__(128) float g_supp[NCLS * FEAT];
__device__ __align__(128) float g_query[NQ * FEAT];
__device__ __align__(128) float g_F[NN * FEAT];          // normalized rows
__device__ float g_nrm[NN];
__device__ __align__(128) float g_sim[NN * NN];          // RAW dot products
__device__ int   g_idx[NN * 81];
__device__ __align__(128) float g_G[NN * NN];
__device__ __align__(128) float g_parts[8 * NN * KPAD];
// activations, BLOCKED: A_blk[kb][80][64] bf16, SW128-swizzled 128B rows
__device__ __align__(1024) __nv_bfloat16 g_xb [NN * KPAD];
__device__ __align__(1024) __nv_bfloat16 g_h1b[NN * HID];
__device__ __align__(1024) __nv_bfloat16 g_h2b[NN * HID];
// weights, BLOCKED: W_blk[nb][kb][32][64] bf16, SW128-swizzled
__device__ __align__(1024) __nv_bfloat16 g_W1b[2][HID * KPAD];
__device__ __align__(1024) __nv_bfloat16 g_W2b[2][HID * HID];
__device__ __align__(1024) __nv_bfloat16 g_W3b[2][KPAD * HID];

#define SW128(o) ((o) ^ (((o) >> 3) & 0x70))
#define ABLK_OFF(m, k) (((k) >> 6) * 10240u + SW128((uint32_t)(((m) << 7) | (((k) & 63) << 1))))

__device__ __forceinline__ void mask_rc(int k, int& r, int& c) {
    int base;
    if      (k < 80)  { r = 0; base = 0;   }
    else if (k < 159) { r = 1; base = 80;  }
    else if (k < 237) { r = 2; base = 159; }
    else if (k < 314) { r = 3; base = 237; }
    else if (k < 390) { r = 4; base = 314; }
    else              { r = 5; base = 390; }
    c = r + 1 + (k - base);
}

// ------------------------- PTX helpers --------------------------------------
__device__ __forceinline__ uint32_t s_u32(const void* p) {
    return (uint32_t)__cvta_generic_to_shared(p);
}
__device__ __forceinline__ void ldsm_x4(uint32_t* r, uint32_t addr) {
    asm volatile("ldmatrix.sync.aligned.m8n8.x4.shared.b16 {%0,%1,%2,%3}, [%4];"
        : "=r"(r[0]), "=r"(r[1]), "=r"(r[2]), "=r"(r[3]) : "r"(addr));
}
__device__ __forceinline__ void ldsm_x2(uint32_t* r, uint32_t addr) {
    asm volatile("ldmatrix.sync.aligned.m8n8.x2.shared.b16 {%0,%1}, [%2];"
        : "=r"(r[0]), "=r"(r[1]) : "r"(addr));
}
__device__ __forceinline__ void mma_bf16(float* d, const uint32_t* a, const uint32_t* b) {
    asm volatile("mma.sync.aligned.m16n8k16.row.col.f32.bf16.bf16.f32 "
        "{%0,%1,%2,%3}, {%4,%5,%6,%7}, {%8,%9}, {%0,%1,%2,%3};"
        : "+f"(d[0]), "+f"(d[1]), "+f"(d[2]), "+f"(d[3])
        : "r"(a[0]), "r"(a[1]), "r"(a[2]), "r"(a[3]), "r"(b[0]), "r"(b[1]));
}
__device__ __forceinline__ void bulkcp(uint32_t dst, const void* src, uint32_t bytes,
                                       uint32_t mbar) {
    asm volatile(
        "cp.async.bulk.shared::cluster.global.mbarrier::complete_tx::bytes [%0], [%1], %2, [%3];"
        :: "r"(dst), "l"(src), "r"(bytes), "r"(mbar) : "memory");
}
__device__ __forceinline__ void mbar_init(uint32_t mbar, uint32_t cnt) {
    asm volatile("mbarrier.init.shared.b64 [%0], %1;" :: "r"(mbar), "r"(cnt) : "memory");
}
__device__ __forceinline__ void mbar_expect(uint32_t mbar, uint32_t tx) {
    asm volatile("mbarrier.arrive.expect_tx.shared.b64 _, [%0], %1;"
                 :: "r"(mbar), "r"(tx) : "memory");
}
#define MWAIT(addr, ph) do { \
    uint32_t _d = 0; \
    while (!_d) { \
        asm volatile("{\n\t.reg .pred p;\n\t" \
            "mbarrier.try_wait.parity.acquire.cta.shared::cta.b64 p, [%1], %2;\n\t" \
            "selp.b32 %0, 1, 0, p;\n\t}" : "=r"(_d) : "r"(addr), "r"(ph)); \
    } } while (0)

// ------------------------- init: supp mean + query copy ---------------------
__global__ void k_init(const float* __restrict__ fs, const float* __restrict__ fq) {
    int idx = blockIdx.x * 256 + threadIdx.x;
    if (idx >= NN * FEAT) return;
    int r = idx / FEAT, d = idx % FEAT;
    if (r < NCLS) {
        float s = 0.f;
        #pragma unroll
        for (int sh = 0; sh < 5; sh++) s += fs[(r * 5 + sh) * FEAT + d];
        g_supp[r * FEAT + d] = s / 5.0f;
    } else {
        g_query[(r - NCLS) * FEAT + d] = fq[(r - NCLS) * FEAT + d];
    }
}

// --------- weight conversion to BLOCKED+SWIZZLED bf16 -----------------------
#define T1 2097152
#define T2 16777216
#define T3 2097152
__global__ void k_convall(const float* s0, const float* s1, const float* s2,
                          const float* s3, const float* s4, const float* s5) {
    long long e = (long long)(blockIdx.x * 256 + threadIdx.x) * 8;
    const float* src; char* dst; long long local; int type;
    if      (e < T1)           { src = s0; dst = (char*)g_W1b[0]; local = e;                  type = 0; }
    else if (e < T1+T2)        { src = s1; dst = (char*)g_W2b[0]; local = e - T1;             type = 1; }
    else if (e < T1+T2+T3)     { src = s2; dst = (char*)g_W3b[0]; local = e - (T1+T2);        type = 2; }
    else if (e < 2*T1+T2+T3)   { src = s3; dst = (char*)g_W1b[1]; local = e - (T1+T2+T3);     type = 0; }
    else if (e < 2*T1+2*T2+T3) { src = s4; dst = (char*)g_W2b[1]; local = e - (2*T1+T2+T3);   type = 1; }
    else                       { src = s5; dst = (char*)g_W3b[1]; local = e - (2*T1+2*T2+T3); type = 2; }
    int K = (type == 0) ? 512 : 4096;
    int n = (int)(local / K);
    int k = (int)(local - (long long)n * K);
    float v[8];
    #pragma unroll
    for (int j = 0; j < 8; j++) {
        bool ok = (type == 0) ? (k + j < DIN) : (type == 2 ? (n < DIN) : true);
        int cols = (type == 0) ? DIN : 4096;
        v[j] = ok ? src[(size_t)n * cols + k + j] : 0.f;
    }
    uint32_t off = ((uint32_t)(n >> 5) * (uint32_t)(K >> 6) + (uint32_t)(k >> 6)) * 4096u
                 + SW128((uint32_t)(((n & 31) << 7) | ((k & 63) << 1)));
    uint32_t o[4];
    #pragma unroll
    for (int j = 0; j < 4; j++) {
        __nv_bfloat162 h;
        h.x = __float2bfloat16(v[2 * j]);
        h.y = __float2bfloat16(v[2 * j + 1]);
        o[j] = *(uint32_t*)&h;
    }
    *(uint4*)(dst + off) = make_uint4(o[0], o[1], o[2], o[3]);
}

// ---------- sim: raw Gram row + own norm + normalized F row -----------------
__global__ void k_sim() {
    int i = blockIdx.x;
    int tid = threadIdx.x;
    __shared__ float Fi[FEAT];
    __shared__ float red[256];
    const float* src = (i < NCLS) ? (g_supp + i * FEAT) : (g_query + (i - NCLS) * FEAT);
    float s = 0.f;
    for (int d = tid; d < FEAT; d += 256) { float v = src[d]; Fi[d] = v; s += v * v; }
    red[tid] = s; __syncthreads();
    for (int o = 128; o > 0; o >>= 1) { if (tid < o) red[tid] += red[tid + o]; __syncthreads(); }
    float nrm = fmaxf(sqrtf(red[0]), 1e-12f);
    if (tid == 0) g_nrm[i] = nrm;
    float inv = 1.f / nrm;
    for (int d = tid; d < FEAT; d += 256) g_F[i * FEAT + d] = Fi[d] * inv;
    int w = tid >> 5, l = tid & 31;
    for (int j = w; j < NN; j += 8) {
        const float* Xj = (j < NCLS) ? (g_supp + j * FEAT) : (g_query + (j - NCLS) * FEAT);
        float p = 0.f;
        for (int d = l; d < FEAT; d += 32) p += Fi[d] * Xj[d];
        #pragma unroll
        for (int o = 16; o > 0; o >>= 1) p += __shfl_xor_sync(0xffffffffu, p, o);
        if (l == 0) g_sim[i * NN + j] = p;
    }
}

// ------- stable rank sort + gather DNI inputs into BLOCKED bf16 -------------
__global__ void k_sortgather() {
    int i = blockIdx.x;
    int tid = threadIdx.x;   // 128
    __shared__ float srow[NN];
    __shared__ float inv[NN];
    __shared__ int a[81];
    for (int j = tid; j < NN; j += 128) inv[j] = 1.f / g_nrm[j];
    __syncthreads();
    float invi = inv[i];
    for (int j = tid; j < NN; j += 128) srow[j] = g_sim[i * NN + j] * invi * inv[j];
    if (tid == 0) a[0] = i;
    __syncthreads();
    if (tid < NCLS) {
        float v = srow[tid];
        int rank = 0;
        #pragma unroll
        for (int j = 0; j < NCLS; j++) {
            float u = srow[j];
            if (j != tid && (u > v || (u == v && j < tid))) rank++;
        }
        a[1 + rank] = tid;
    }
    if (tid < NQ) {
        float v = srow[NCLS + tid];
        int rank = 0;
        for (int j = 0; j < NQ; j++) {
            float u = srow[NCLS + j];
            if (u > v || (u == v && j < tid)) rank++;
        }
        a[6 + rank] = NCLS + tid;
    }
    __syncthreads();
    for (int t = tid; t < 81; t += 128) g_idx[i * 81 + t] = a[t];
    char* xb = (char*)g_xb;
    for (int k = tid; k < KPAD; k += 128) {
        float v = 0.f;
        if (k < DIN) {
            int r, c; mask_rc(k, r, c);
            v = g_sim[a[r] * NN + a[c]] * inv[a[r]] * inv[a[c]];
        }
        *(__nv_bfloat16*)(xb + ABLK_OFF(i, k)) = __float2bfloat16(v);
    }
    for (int t = tid; t < NN; t += 128) g_G[i * NN + t] = 0.f;
}

// ========= bulk-loaded mma.sync GEMM: 512 thr, 4 kgroups x 4 n-warps ========
// D[80 x 32] = A[80 x Kchunk] * W[32 x Kchunk]^T at (nb=blockIdx.x, sk=blockIdx.y)
// stage = 4 x [A 10240 | W 4096] = 57344B, 3 stages.
#define KGB 14336
#define STB 57344
#define GSMEM (3 * STB + 1024)
template<int MODE>
__global__ void __launch_bounds__(512) k_gemmB(
    const char* __restrict__ Ablk, const char* __restrict__ Wblk,
    int KbTotal, int Kchunk, const float* __restrict__ bias,
    void* __restrict__ Cout, int partStride)
{
    extern __shared__ char dyn[];
    __shared__ uint64_t mbar[3];
    const int tid = threadIdx.x, w = tid >> 5, l = tid & 31;
    const int kg = w >> 2, nw = w & 3;
    const int nb = blockIdx.x;
    const int k0 = blockIdx.y * Kchunk;
    const int kgK = Kchunk >> 2;
    const int nIt = kgK >> 6;
    const uint32_t sbase = (s_u32(dyn) + 1023u) & ~1023u;
    char* dalign = (char*)(((uintptr_t)dyn + 1023ull) & ~1023ull);

    if (tid == 0) {
        #pragma unroll
        for (int i = 0; i < 3; i++) mbar_init(s_u32(&mbar[i]), 1);
    }
    __syncthreads();

    auto issue = [&](int it, int s) {
        uint32_t st = sbase + s * STB;
        uint32_t mb = s_u32(&mbar[s]);
        mbar_expect(mb, STB);
        #pragma unroll
        for (int g = 0; g < 4; g++) {
            int kb = ((k0 + g * kgK) >> 6) + it;
            bulkcp(st + g * KGB,         Ablk + (size_t)kb * 10240, 10240, mb);
            bulkcp(st + g * KGB + 10240, Wblk + ((size_t)nb * KbTotal + kb) * 4096, 4096, mb);
        }
    };

    if (tid == 0) {
        int npre = (nIt < 3) ? nIt : 3;
        for (int c = 0; c < npre; c++) issue(c, c);
    }

    float acc[5][4];
    #pragma unroll
    for (int mt = 0; mt < 5; mt++)
        #pragma unroll
        for (int q = 0; q < 4; q++) acc[mt][q] = 0.f;

    const int arow = (l & 7) + 8 * ((l >> 3) & 1);
    const int acolB = 16 * (l >> 4);
    const int brow = (l & 7);
    const int bcolB = 16 * ((l >> 3) & 1);

    int ph[3] = {0, 0, 0};
    for (int it = 0; it < nIt; it++) {
        int s = it % 3;
        MWAIT(s_u32(&mbar[s]), ph[s]); ph[s] ^= 1;
        uint32_t A0 = sbase + s * STB + kg * KGB;
        uint32_t W0 = A0 + 10240;
        #pragma unroll
        for (int ks = 0; ks < 4; ks++) {
            uint32_t kb = ks * 32;
            uint32_t b[2];
            ldsm_x2(b, W0 + SW128((uint32_t)((nw * 8 + brow) * 128) + kb + bcolB));
            #pragma unroll
            for (int mt = 0; mt < 5; mt++) {
                uint32_t a[4];
                ldsm_x4(a, A0 + SW128((uint32_t)((mt * 16 + arow) * 128) + kb + acolB));
                mma_bf16(acc[mt], a, b);
            }
        }
        __syncthreads();
        if (tid == 0 && it + 3 < nIt) issue(it + 3, s);
    }

    // reduce 4 kgroups: kg 1..3 write scratch, kg 0 accumulates + stores
    float* scr = (float*)dalign;   // 3 x 2560 floats = 30KB
    __syncthreads();
    if (kg > 0) {
        float* sp = scr + (kg - 1) * 2560;
        #pragma unroll
        for (int mt = 0; mt < 5; mt++)
            #pragma unroll
            for (int q = 0; q < 4; q++)
                sp[((nw * 5 + mt) * 32 + l) * 4 + q] = acc[mt][q];
    }
    __syncthreads();
    if (kg == 0) {
        int n = nb * 32 + nw * 8 + 2 * (l & 3);
        #pragma unroll
        for (int mt = 0; mt < 5; mt++) {
            float v[4];
            #pragma unroll
            for (int q = 0; q < 4; q++) {
                int idx = ((nw * 5 + mt) * 32 + l) * 4 + q;
                v[q] = acc[mt][q] + scr[idx] + scr[2560 + idx] + scr[5120 + idx];
            }
            int m0 = mt * 16 + (l >> 2);
            if (MODE == 0) {
                char* H = (char*)Cout;
                float b0 = bias[n], b1 = bias[n + 1];
                __nv_bfloat162 h0, h1;
                h0.x = __float2bfloat16(fmaxf(v[0] + b0, 0.f));
                h0.y = __float2bfloat16(fmaxf(v[1] + b1, 0.f));
                h1.x = __float2bfloat16(fmaxf(v[2] + b0, 0.f));
                h1.y = __float2bfloat16(fmaxf(v[3] + b1, 0.f));
                *(__nv_bfloat162*)(H + ABLK_OFF(m0, n))     = h0;
                *(__nv_bfloat162*)(H + ABLK_OFF(m0 + 8, n)) = h1;
            } else {
                float* Cp = (float*)Cout + (size_t)blockIdx.y * partStride;
                *(float2*)&Cp[(size_t)m0 * KPAD + n]       = make_float2(v[0], v[1]);
                *(float2*)&Cp[(size_t)(m0 + 8) * KPAD + n] = make_float2(v[2], v[3]);
            }
        }
    }
}

// ------ scatter: G += g at (a_r,a_c),(a_c,a_r); g = sum8(parts)+b3 ----------
__global__ void k_scatter(const float* __restrict__ b3) {
    int i = blockIdx.x;
    int tid = threadIdx.x;   // 128
    __shared__ int a[81];
    for (int t = tid; t < 81; t += 128) a[t] = g_idx[i * 81 + t];
    __syncthreads();
    for (int k = tid; k < DIN; k += 128) {
        float v = b3[k];
        #pragma unroll
        for (int s = 0; s < 8; s++) v += g_parts[(size_t)s * NN * KPAD + i * KPAD + k];
        int r, c; mask_rc(k, r, c);
        atomicAdd(&g_G[a[r] * NN + a[c]], v);
        atomicAdd(&g_G[a[c] * NN + a[r]], v);
    }
}

// --------- Fbar = Gbar F; normalize-VJP; SGD update -------------------------
__global__ void k_update(int lo, float* __restrict__ target) {
    int p = lo + blockIdx.x;
    int tid = threadIdx.x;
    __shared__ float Gp[NN];
    __shared__ float fb[FEAT];
    __shared__ float red[256];
    for (int q = tid; q < NN; q += 256) Gp[q] = g_G[p * NN + q];
    __syncthreads();
    for (int d = tid; d < FEAT; d += 256) {
        float s = 0.f;
        #pragma unroll 8
        for (int q = 0; q < NN; q++) s += Gp[q] * g_F[q * FEAT + d];
        fb[d] = s;
    }
    __syncthreads();
    float part = 0.f;
    for (int d = tid; d < FEAT; d += 256) part += fb[d] * g_F[p * FEAT + d];
    red[tid] = part; __syncthreads();
    for (int o = 128; o > 0; o >>= 1) { if (tid < o) red[tid] += red[tid + o]; __syncthreads(); }
    float dot = red[0];
    float inv = 1.f / g_nrm[p];
    for (int d = tid; d < FEAT; d += 256) {
        float fp = g_F[p * FEAT + d];
        float dX = (fb[d] - dot * fp) * inv;
        target[(p - lo) * FEAT + d] -= LRC * dX;
    }
}

// ------------- final: normalize from raw + (sim_sq * scale)^T ---------------
__global__ void k_final(const float* __restrict__ scale, float* __restrict__ out) {
    int q = blockIdx.x;
    int tid = threadIdx.x;
    __shared__ float Fq[FEAT];
    __shared__ float red[256];
    const float* qr = g_query + q * FEAT;
    float s = 0.f;
    for (int d = tid; d < FEAT; d += 256) { float v = qr[d]; Fq[d] = v; s += v * v; }
    red[tid] = s; __syncthreads();
    for (int o = 128; o > 0; o >>= 1) { if (tid < o) red[tid] += red[tid + o]; __syncthreads(); }
    float nq = fmaxf(sqrtf(red[0]), 1e-12f);
    int w = tid >> 5, l = tid & 31;
    if (w < NCLS) {
        const float* sr = g_supp + w * FEAT;
        float dt = 0.f, s2 = 0.f;
        for (int d = l; d < FEAT; d += 32) {
            float sv = sr[d];
            dt += sv * Fq[d];
            s2 += sv * sv;
        }
        #pragma unroll
        for (int o = 16; o > 0; o >>= 1) {
            dt += __shfl_xor_sync(0xffffffffu, dt, o);
            s2 += __shfl_xor_sync(0xffffffffu, s2, o);
        }
        if (l == 0) {
            float ns = fmaxf(sqrtf(s2), 1e-12f);
            out[q * NCLS + w] = dt / (ns * nq) * scale[0];
        }
    }
}

// ----------------------------------------------------------------------------
extern "C" void kernel_launch(void* const* d_in, const int* in_sizes, int n_in,
                              void* d_out, int out_size) {
    const float* fs    = (const float*)d_in[0];
    const float* fq    = (const float*)d_in[1];
    const float* scale = (const float*)d_in[2];

    float *pp, *ps, *pq;
    char *pxb, *ph1b, *ph2b, *pw1b, *pw2b, *pw3b;
    cudaGetSymbolAddress((void**)&pp,   g_parts);
    cudaGetSymbolAddress((void**)&ps,   g_supp);
    cudaGetSymbolAddress((void**)&pq,   g_query);
    cudaGetSymbolAddress((void**)&pxb,  g_xb);
    cudaGetSymbolAddress((void**)&ph1b, g_h1b);
    cudaGetSymbolAddress((void**)&ph2b, g_h2b);
    cudaGetSymbolAddress((void**)&pw1b, g_W1b);
    cudaGetSymbolAddress((void**)&pw2b, g_W2b);
    cudaGetSymbolAddress((void**)&pw3b, g_W3b);

    cudaFuncSetAttribute(k_gemmB<0>, cudaFuncAttributeMaxDynamicSharedMemorySize, GSMEM);
    cudaFuncSetAttribute(k_gemmB<1>, cudaFuncAttributeMaxDynamicSharedMemorySize, GSMEM);

    k_init<<<200, 256>>>(fs, fq);
    k_convall<<<20480, 256>>>(
        (const float*)d_in[3],  (const float*)d_in[5],  (const float*)d_in[7],
        (const float*)d_in[9],  (const float*)d_in[11], (const float*)d_in[13]);

    for (int step = 0; step < 3; step++) {
        for (int br = 0; br < 2; br++) {
            const float* b1 = (const float*)d_in[3 + 6 * br + 1];
            const float* b2 = (const float*)d_in[3 + 6 * br + 3];
            const float* b3 = (const float*)d_in[3 + 6 * br + 5];
            char* W1b = pw1b + (size_t)br * T1 * 2;
            char* W2b = pw2b + (size_t)br * T2 * 2;
            char* W3b = pw3b + (size_t)br * T3 * 2;

            k_sim<<<NN, 256>>>();
            k_sortgather<<<NN, 128>>>();

            // L1: K=512 (kgK=128, nIt=2), N=4096 -> 128 n-blocks
            k_gemmB<0><<<dim3(128, 1), 512, GSMEM>>>(pxb, W1b, 8, 512, b1, ph1b, 0);
            // L2: K=4096 (kgK=1024, nIt=16), N=4096
            k_gemmB<0><<<dim3(128, 1), 512, GSMEM>>>(ph1b, W2b, 64, 4096, b2, ph2b, 0);
            // L3: N=512 (16 n-blocks), splitK=8 (Kchunk=512)
            k_gemmB<1><<<dim3(16, 8), 512, GSMEM>>>(ph2b, W3b, 64, 512, nullptr, pp, NN * KPAD);

            k_scatter<<<NN, 128>>>(b3);
            if (br == 0) k_update<<<NCLS, 256>>>(0, ps);
            else         k_update<<<NQ, 256>>>(NCLS, pq);
        }
    }

    k_final<<<NQ, 256>>>(scale, (float*)d_out);
}

// round 9
// speedup vs baseline: 1.3246x; 1.0039x over previous
#include <cuda_runtime.h>
#include <cuda_bf16.h>
#include <math.h>
#include <stdint.h>

#define NCLS 5
#define NQ   75
#define NN   80
#define FEAT 640
#define HID  4096
#define DIN  465
#define KPAD 512
#define LRC  1e-3f

// ------------------------- scratch (device globals) -------------------------
__device__ __align__(128) float g_supp[NCLS * FEAT];
__device__ __align__(128) float g_query[NQ * FEAT];
__device__ __align__(128) float g_F[NN * FEAT];          // normalized rows
__device__ float g_nrm[NN];
__device__ __align__(128) float g_sim[NN * NN];          // RAW dot products
__device__ int   g_idx[NN * 81];
__device__ __align__(128) float g_G[NN * NN];
__device__ __align__(128) float g_parts[8 * NN * KPAD];
// activations, BLOCKED: A_blk[kb][80][64] bf16, SW128-swizzled 128B rows
__device__ __align__(1024) __nv_bfloat16 g_xb [NN * KPAD];
__device__ __align__(1024) __nv_bfloat16 g_h1b[NN * HID];
__device__ __align__(1024) __nv_bfloat16 g_h2b[NN * HID];
// weights, BLOCKED: W_blk[nb][kb][32][64] bf16, SW128-swizzled
__device__ __align__(1024) __nv_bfloat16 g_W1b[2][HID * KPAD];
__device__ __align__(1024) __nv_bfloat16 g_W2b[2][HID * HID];
__device__ __align__(1024) __nv_bfloat16 g_W3b[2][KPAD * HID];

#define SW128(o) ((o) ^ (((o) >> 3) & 0x70))
#define ABLK_OFF(m, k) (((k) >> 6) * 10240u + SW128((uint32_t)(((m) << 7) | (((k) & 63) << 1))))

__device__ __forceinline__ void mask_rc(int k, int& r, int& c) {
    int base;
    if      (k < 80)  { r = 0; base = 0;   }
    else if (k < 159) { r = 1; base = 80;  }
    else if (k < 237) { r = 2; base = 159; }
    else if (k < 314) { r = 3; base = 237; }
    else if (k < 390) { r = 4; base = 314; }
    else              { r = 5; base = 390; }
    c = r + 1 + (k - base);
}

// ------------------------- PTX helpers --------------------------------------
__device__ __forceinline__ uint32_t s_u32(const void* p) {
    return (uint32_t)__cvta_generic_to_shared(p);
}
__device__ __forceinline__ void ldsm_x4(uint32_t* r, uint32_t addr) {
    asm volatile("ldmatrix.sync.aligned.m8n8.x4.shared.b16 {%0,%1,%2,%3}, [%4];"
        : "=r"(r[0]), "=r"(r[1]), "=r"(r[2]), "=r"(r[3]) : "r"(addr));
}
__device__ __forceinline__ void ldsm_x2(uint32_t* r, uint32_t addr) {
    asm volatile("ldmatrix.sync.aligned.m8n8.x2.shared.b16 {%0,%1}, [%2];"
        : "=r"(r[0]), "=r"(r[1]) : "r"(addr));
}
__device__ __forceinline__ void mma_bf16(float* d, const uint32_t* a, const uint32_t* b) {
    asm volatile("mma.sync.aligned.m16n8k16.row.col.f32.bf16.bf16.f32 "
        "{%0,%1,%2,%3}, {%4,%5,%6,%7}, {%8,%9}, {%0,%1,%2,%3};"
        : "+f"(d[0]), "+f"(d[1]), "+f"(d[2]), "+f"(d[3])
        : "r"(a[0]), "r"(a[1]), "r"(a[2]), "r"(a[3]), "r"(b[0]), "r"(b[1]));
}
__device__ __forceinline__ void bulkcp(uint32_t dst, const void* src, uint32_t bytes,
                                       uint32_t mbar) {
    asm volatile(
        "cp.async.bulk.shared::cluster.global.mbarrier::complete_tx::bytes [%0], [%1], %2, [%3];"
        :: "r"(dst), "l"(src), "r"(bytes), "r"(mbar) : "memory");
}
__device__ __forceinline__ void mbar_init(uint32_t mbar, uint32_t cnt) {
    asm volatile("mbarrier.init.shared.b64 [%0], %1;" :: "r"(mbar), "r"(cnt) : "memory");
}
__device__ __forceinline__ void mbar_expect(uint32_t mbar, uint32_t tx) {
    asm volatile("mbarrier.arrive.expect_tx.shared.b64 _, [%0], %1;"
                 :: "r"(mbar), "r"(tx) : "memory");
}
#define MWAIT(addr, ph) do { \
    uint32_t _d = 0; \
    while (!_d) { \
        asm volatile("{\n\t.reg .pred p;\n\t" \
            "mbarrier.try_wait.parity.acquire.cta.shared::cta.b64 p, [%1], %2;\n\t" \
            "selp.b32 %0, 1, 0, p;\n\t}" : "=r"(_d) : "r"(addr), "r"(ph)); \
    } } while (0)

// ------------------------- init: supp mean + query copy ---------------------
__global__ void k_init(const float* __restrict__ fs, const float* __restrict__ fq) {
    int idx = blockIdx.x * 256 + threadIdx.x;
    if (idx >= NN * FEAT) return;
    int r = idx / FEAT, d = idx % FEAT;
    if (r < NCLS) {
        float s = 0.f;
        #pragma unroll
        for (int sh = 0; sh < 5; sh++) s += fs[(r * 5 + sh) * FEAT + d];
        g_supp[r * FEAT + d] = s / 5.0f;
    } else {
        g_query[(r - NCLS) * FEAT + d] = fq[(r - NCLS) * FEAT + d];
    }
}

// --------- weight conversion to BLOCKED+SWIZZLED bf16 -----------------------
#define T1 2097152
#define T2 16777216
#define T3 2097152
__global__ void k_convall(const float* s0, const float* s1, const float* s2,
                          const float* s3, const float* s4, const float* s5) {
    long long e = (long long)(blockIdx.x * 256 + threadIdx.x) * 8;
    const float* src; char* dst; long long local; int type;
    if      (e < T1)           { src = s0; dst = (char*)g_W1b[0]; local = e;                  type = 0; }
    else if (e < T1+T2)        { src = s1; dst = (char*)g_W2b[0]; local = e - T1;             type = 1; }
    else if (e < T1+T2+T3)     { src = s2; dst = (char*)g_W3b[0]; local = e - (T1+T2);        type = 2; }
    else if (e < 2*T1+T2+T3)   { src = s3; dst = (char*)g_W1b[1]; local = e - (T1+T2+T3);     type = 0; }
    else if (e < 2*T1+2*T2+T3) { src = s4; dst = (char*)g_W2b[1]; local = e - (2*T1+T2+T3);   type = 1; }
    else                       { src = s5; dst = (char*)g_W3b[1]; local = e - (2*T1+2*T2+T3); type = 2; }
    int K = (type == 0) ? 512 : 4096;
    int n = (int)(local / K);
    int k = (int)(local - (long long)n * K);
    float v[8];
    #pragma unroll
    for (int j = 0; j < 8; j++) {
        bool ok = (type == 0) ? (k + j < DIN) : (type == 2 ? (n < DIN) : true);
        int cols = (type == 0) ? DIN : 4096;
        v[j] = ok ? src[(size_t)n * cols + k + j] : 0.f;
    }
    uint32_t off = ((uint32_t)(n >> 5) * (uint32_t)(K >> 6) + (uint32_t)(k >> 6)) * 4096u
                 + SW128((uint32_t)(((n & 31) << 7) | ((k & 63) << 1)));
    uint32_t o[4];
    #pragma unroll
    for (int j = 0; j < 4; j++) {
        __nv_bfloat162 h;
        h.x = __float2bfloat16(v[2 * j]);
        h.y = __float2bfloat16(v[2 * j + 1]);
        o[j] = *(uint32_t*)&h;
    }
    *(uint4*)(dst + off) = make_uint4(o[0], o[1], o[2], o[3]);
}

// ---------- sim: raw Gram row + own norm + normalized F row -----------------
__global__ void k_sim() {
    int i = blockIdx.x;
    int tid = threadIdx.x;
    __shared__ float Fi[FEAT];
    __shared__ float red[256];
    const float* src = (i < NCLS) ? (g_supp + i * FEAT) : (g_query + (i - NCLS) * FEAT);
    float s = 0.f;
    for (int d = tid; d < FEAT; d += 256) { float v = src[d]; Fi[d] = v; s += v * v; }
    red[tid] = s; __syncthreads();
    for (int o = 128; o > 0; o >>= 1) { if (tid < o) red[tid] += red[tid + o]; __syncthreads(); }
    float nrm = fmaxf(sqrtf(red[0]), 1e-12f);
    if (tid == 0) g_nrm[i] = nrm;
    float inv = 1.f / nrm;
    for (int d = tid; d < FEAT; d += 256) g_F[i * FEAT + d] = Fi[d] * inv;
    int w = tid >> 5, l = tid & 31;
    for (int j = w; j < NN; j += 8) {
        const float* Xj = (j < NCLS) ? (g_supp + j * FEAT) : (g_query + (j - NCLS) * FEAT);
        float p = 0.f;
        for (int d = l; d < FEAT; d += 32) p += Fi[d] * Xj[d];
        #pragma unroll
        for (int o = 16; o > 0; o >>= 1) p += __shfl_xor_sync(0xffffffffu, p, o);
        if (l == 0) g_sim[i * NN + j] = p;
    }
}

// ------- stable rank sort + gather DNI inputs into BLOCKED bf16 -------------
__global__ void k_sortgather() {
    int i = blockIdx.x;
    int tid = threadIdx.x;   // 128
    __shared__ float srow[NN];
    __shared__ float inv[NN];
    __shared__ int a[81];
    for (int j = tid; j < NN; j += 128) inv[j] = 1.f / g_nrm[j];
    __syncthreads();
    float invi = inv[i];
    for (int j = tid; j < NN; j += 128) srow[j] = g_sim[i * NN + j] * invi * inv[j];
    if (tid == 0) a[0] = i;
    __syncthreads();
    if (tid < NCLS) {
        float v = srow[tid];
        int rank = 0;
        #pragma unroll
        for (int j = 0; j < NCLS; j++) {
            float u = srow[j];
            if (j != tid && (u > v || (u == v && j < tid))) rank++;
        }
        a[1 + rank] = tid;
    }
    if (tid < NQ) {
        float v = srow[NCLS + tid];
        int rank = 0;
        for (int j = 0; j < NQ; j++) {
            float u = srow[NCLS + j];
            if (u > v || (u == v && j < tid)) rank++;
        }
        a[6 + rank] = NCLS + tid;
    }
    __syncthreads();
    for (int t = tid; t < 81; t += 128) g_idx[i * 81 + t] = a[t];
    char* xb = (char*)g_xb;
    for (int k = tid; k < KPAD; k += 128) {
        float v = 0.f;
        if (k < DIN) {
            int r, c; mask_rc(k, r, c);
            v = g_sim[a[r] * NN + a[c]] * inv[a[r]] * inv[a[c]];
        }
        *(__nv_bfloat16*)(xb + ABLK_OFF(i, k)) = __float2bfloat16(v);
    }
    for (int t = tid; t < NN; t += 128) g_G[i * NN + t] = 0.f;
}

// ========= bulk-loaded mma.sync GEMM: 512 thr, 4 kgroups x 4 n-warps ========
// D[80 x 32] = A[80 x Kchunk] * W[32 x Kchunk]^T at (nb=blockIdx.x, sk=blockIdx.y)
// stage = 4 x [A 10240 | W 4096] = 57344B, 3 stages.
#define KGB 14336
#define STB 57344
#define GSMEM (3 * STB + 1024)
template<int MODE>
__global__ void __launch_bounds__(512) k_gemmB(
    const char* __restrict__ Ablk, const char* __restrict__ Wblk,
    int KbTotal, int Kchunk, const float* __restrict__ bias,
    void* __restrict__ Cout, int partStride)
{
    extern __shared__ char dyn[];
    __shared__ uint64_t mbar[3];
    const int tid = threadIdx.x, w = tid >> 5, l = tid & 31;
    const int kg = w >> 2, nw = w & 3;
    const int nb = blockIdx.x;
    const int k0 = blockIdx.y * Kchunk;
    const int kgK = Kchunk >> 2;
    const int nIt = kgK >> 6;
    const uint32_t sbase = (s_u32(dyn) + 1023u) & ~1023u;
    char* dalign = (char*)(((uintptr_t)dyn + 1023ull) & ~1023ull);

    if (tid == 0) {
        #pragma unroll
        for (int i = 0; i < 3; i++) mbar_init(s_u32(&mbar[i]), 1);
    }
    __syncthreads();

    auto issue = [&](int it, int s) {
        uint32_t st = sbase + s * STB;
        uint32_t mb = s_u32(&mbar[s]);
        mbar_expect(mb, STB);
        #pragma unroll
        for (int g = 0; g < 4; g++) {
            int kb = ((k0 + g * kgK) >> 6) + it;
            bulkcp(st + g * KGB,         Ablk + (size_t)kb * 10240, 10240, mb);
            bulkcp(st + g * KGB + 10240, Wblk + ((size_t)nb * KbTotal + kb) * 4096, 4096, mb);
        }
    };

    if (tid == 0) {
        int npre = (nIt < 3) ? nIt : 3;
        for (int c = 0; c < npre; c++) issue(c, c);
    }

    float acc[5][4];
    #pragma unroll
    for (int mt = 0; mt < 5; mt++)
        #pragma unroll
        for (int q = 0; q < 4; q++) acc[mt][q] = 0.f;

    const int arow = (l & 7) + 8 * ((l >> 3) & 1);
    const int acolB = 16 * (l >> 4);
    const int brow = (l & 7);
    const int bcolB = 16 * ((l >> 3) & 1);

    int ph[3] = {0, 0, 0};
    for (int it = 0; it < nIt; it++) {
        int s = it % 3;
        MWAIT(s_u32(&mbar[s]), ph[s]); ph[s] ^= 1;
        uint32_t A0 = sbase + s * STB + kg * KGB;
        uint32_t W0 = A0 + 10240;
        #pragma unroll
        for (int ks = 0; ks < 4; ks++) {
            uint32_t kb = ks * 32;
            uint32_t b[2];
            ldsm_x2(b, W0 + SW128((uint32_t)((nw * 8 + brow) * 128) + kb + bcolB));
            #pragma unroll
            for (int mt = 0; mt < 5; mt++) {
                uint32_t a[4];
                ldsm_x4(a, A0 + SW128((uint32_t)((mt * 16 + arow) * 128) + kb + acolB));
                mma_bf16(acc[mt], a, b);
            }
        }
        __syncthreads();
        if (tid == 0 && it + 3 < nIt) issue(it + 3, s);
    }

    // reduce 4 kgroups: kg 1..3 write scratch, kg 0 accumulates + stores
    float* scr = (float*)dalign;   // 3 x 2560 floats = 30KB
    __syncthreads();
    if (kg > 0) {
        float* sp = scr + (kg - 1) * 2560;
        #pragma unroll
        for (int mt = 0; mt < 5; mt++)
            #pragma unroll
            for (int q = 0; q < 4; q++)
                sp[((nw * 5 + mt) * 32 + l) * 4 + q] = acc[mt][q];
    }
    __syncthreads();
    if (kg == 0) {
        int n = nb * 32 + nw * 8 + 2 * (l & 3);
        #pragma unroll
        for (int mt = 0; mt < 5; mt++) {
            float v[4];
            #pragma unroll
            for (int q = 0; q < 4; q++) {
                int idx = ((nw * 5 + mt) * 32 + l) * 4 + q;
                v[q] = acc[mt][q] + scr[idx] + scr[2560 + idx] + scr[5120 + idx];
            }
            int m0 = mt * 16 + (l >> 2);
            if (MODE == 0) {
                char* H = (char*)Cout;
                float b0 = bias[n], b1 = bias[n + 1];
                __nv_bfloat162 h0, h1;
                h0.x = __float2bfloat16(fmaxf(v[0] + b0, 0.f));
                h0.y = __float2bfloat16(fmaxf(v[1] + b1, 0.f));
                h1.x = __float2bfloat16(fmaxf(v[2] + b0, 0.f));
                h1.y = __float2bfloat16(fmaxf(v[3] + b1, 0.f));
                *(__nv_bfloat162*)(H + ABLK_OFF(m0, n))     = h0;
                *(__nv_bfloat162*)(H + ABLK_OFF(m0 + 8, n)) = h1;
            } else {
                float* Cp = (float*)Cout + (size_t)blockIdx.y * partStride;
                *(float2*)&Cp[(size_t)m0 * KPAD + n]       = make_float2(v[0], v[1]);
                *(float2*)&Cp[(size_t)(m0 + 8) * KPAD + n] = make_float2(v[2], v[3]);
            }
        }
    }
}

// ------ scatter: G += g at (a_r,a_c),(a_c,a_r); g = sum8(parts)+b3 ----------
__global__ void k_scatter(const float* __restrict__ b3) {
    int i = blockIdx.x;
    int tid = threadIdx.x;   // 128
    __shared__ int a[81];
    for (int t = tid; t < 81; t += 128) a[t] = g_idx[i * 81 + t];
    __syncthreads();
    for (int k = tid; k < DIN; k += 128) {
        float v = b3[k];
        #pragma unroll
        for (int s = 0; s < 8; s++) v += g_parts[(size_t)s * NN * KPAD + i * KPAD + k];
        int r, c; mask_rc(k, r, c);
        atomicAdd(&g_G[a[r] * NN + a[c]], v);
        atomicAdd(&g_G[a[c] * NN + a[r]], v);
    }
}

// --------- Fbar = Gbar F; normalize-VJP; SGD update -------------------------
__global__ void k_update(int lo, float* __restrict__ target) {
    int p = lo + blockIdx.x;
    int tid = threadIdx.x;
    __shared__ float Gp[NN];
    __shared__ float fb[FEAT];
    __shared__ float red[256];
    for (int q = tid; q < NN; q += 256) Gp[q] = g_G[p * NN + q];
    __syncthreads();
    for (int d = tid; d < FEAT; d += 256) {
        float s = 0.f;
        #pragma unroll 8
        for (int q = 0; q < NN; q++) s += Gp[q] * g_F[q * FEAT + d];
        fb[d] = s;
    }
    __syncthreads();
    float part = 0.f;
    for (int d = tid; d < FEAT; d += 256) part += fb[d] * g_F[p * FEAT + d];
    red[tid] = part; __syncthreads();
    for (int o = 128; o > 0; o >>= 1) { if (tid < o) red[tid] += red[tid + o]; __syncthreads(); }
    float dot = red[0];
    float inv = 1.f / g_nrm[p];
    for (int d = tid; d < FEAT; d += 256) {
        float fp = g_F[p * FEAT + d];
        float dX = (fb[d] - dot * fp) * inv;
        target[(p - lo) * FEAT + d] -= LRC * dX;
    }
}

// ------------- final: normalize from raw + (sim_sq * scale)^T ---------------
__global__ void k_final(const float* __restrict__ scale, float* __restrict__ out) {
    int q = blockIdx.x;
    int tid = threadIdx.x;
    __shared__ float Fq[FEAT];
    __shared__ float red[256];
    const float* qr = g_query + q * FEAT;
    float s = 0.f;
    for (int d = tid; d < FEAT; d += 256) { float v = qr[d]; Fq[d] = v; s += v * v; }
    red[tid] = s; __syncthreads();
    for (int o = 128; o > 0; o >>= 1) { if (tid < o) red[tid] += red[tid + o]; __syncthreads(); }
    float nq = fmaxf(sqrtf(red[0]), 1e-12f);
    int w = tid >> 5, l = tid & 31;
    if (w < NCLS) {
        const float* sr = g_supp + w * FEAT;
        float dt = 0.f, s2 = 0.f;
        for (int d = l; d < FEAT; d += 32) {
            float sv = sr[d];
            dt += sv * Fq[d];
            s2 += sv * sv;
        }
        #pragma unroll
        for (int o = 16; o > 0; o >>= 1) {
            dt += __shfl_xor_sync(0xffffffffu, dt, o);
            s2 += __shfl_xor_sync(0xffffffffu, s2, o);
        }
        if (l == 0) {
            float ns = fmaxf(sqrtf(s2), 1e-12f);
            out[q * NCLS + w] = dt / (ns * nq) * scale[0];
        }
    }
}

// ----------------------------------------------------------------------------
extern "C" void kernel_launch(void* const* d_in, const int* in_sizes, int n_in,
                              void* d_out, int out_size) {
    const float* fs    = (const float*)d_in[0];
    const float* fq    = (const float*)d_in[1];
    const float* scale = (const float*)d_in[2];

    float *pp, *ps, *pq;
    char *pxb, *ph1b, *ph2b, *pw1b, *pw2b, *pw3b;
    cudaGetSymbolAddress((void**)&pp,   g_parts);
    cudaGetSymbolAddress((void**)&ps,   g_supp);
    cudaGetSymbolAddress((void**)&pq,   g_query);
    cudaGetSymbolAddress((void**)&pxb,  g_xb);
    cudaGetSymbolAddress((void**)&ph1b, g_h1b);
    cudaGetSymbolAddress((void**)&ph2b, g_h2b);
    cudaGetSymbolAddress((void**)&pw1b, g_W1b);
    cudaGetSymbolAddress((void**)&pw2b, g_W2b);
    cudaGetSymbolAddress((void**)&pw3b, g_W3b);

    cudaFuncSetAttribute(k_gemmB<0>, cudaFuncAttributeMaxDynamicSharedMemorySize, GSMEM);
    cudaFuncSetAttribute(k_gemmB<1>, cudaFuncAttributeMaxDynamicSharedMemorySize, GSMEM);

    k_init<<<200, 256>>>(fs, fq);
    k_convall<<<20480, 256>>>(
        (const float*)d_in[3],  (const float*)d_in[5],  (const float*)d_in[7],
        (const float*)d_in[9],  (const float*)d_in[11], (const float*)d_in[13]);

    for (int step = 0; step < 3; step++) {
        for (int br = 0; br < 2; br++) {
            const float* b1 = (const float*)d_in[3 + 6 * br + 1];
            const float* b2 = (const float*)d_in[3 + 6 * br + 3];
            const float* b3 = (const float*)d_in[3 + 6 * br + 5];
            char* W1b = pw1b + (size_t)br * T1 * 2;
            char* W2b = pw2b + (size_t)br * T2 * 2;
            char* W3b = pw3b + (size_t)br * T3 * 2;

            k_sim<<<NN, 256>>>();
            k_sortgather<<<NN, 128>>>();

            // L1: K=512 (kgK=128, nIt=2), N=4096 -> 128 n-blocks
            k_gemmB<0><<<dim3(128, 1), 512, GSMEM>>>(pxb, W1b, 8, 512, b1, ph1b, 0);
            // L2: K=4096 (kgK=1024, nIt=16), N=4096
            k_gemmB<0><<<dim3(128, 1), 512, GSMEM>>>(ph1b, W2b, 64, 4096, b2, ph2b, 0);
            // L3: N=512 (16 n-blocks), splitK=8 (Kchunk=512)
            k_gemmB<1><<<dim3(16, 8), 512, GSMEM>>>(ph2b, W3b, 64, 512, nullptr, pp, NN * KPAD);

            k_scatter<<<NN, 128>>>(b3);
            if (br == 0) k_update<<<NCLS, 256>>>(0, ps);
            else         k_update<<<NQ, 256>>>(NCLS, pq);
        }
    }

    k_final<<<NQ, 256>>>(scale, (float*)d_out);
}